// round 12
// baseline (speedup 1.0000x reference)
#include <cuda_runtime.h>
#include <cuda_fp16.h>
#include <cstdint>
#include <math.h>

// Problem dims
#define T_DIM 1024
#define B_DIM 16
#define H_DIM 1024
#define L_DIM 3
#define M_DIM (T_DIM * B_DIM)   // 16384
#define N_DIM (3 * H_DIM)       // 3072
#define K_DIM H_DIM             // 1024
#define NCH   (B_DIM * H_DIM)   // 16384 scan channels
#define NPAIR (NCH / 2)         // 8192 channel pairs

// GEMM tiling (fp16 operands, fp32 accum) — best-known shape (R7/R9)
#define BM 128
#define BN 128
#define BK 64
#define K_ITERS (K_DIM / BK)     // 16
#define WM 64
#define WN 32
#define MT (WM / 16)             // 4
#define NT (WN / 8)              // 4
#define ROWB 144                 // bytes per SMEM row (72 halves, padded)
#define TILE_BYTES (128 * ROWB)
#define STAGE_BYTES (2 * TILE_BYTES)
#define STAGES 3
#define SM_TOTAL (STAGES * STAGE_BYTES)    // 110592

// Scan chunking
#define S_CHUNKS 16
#define CHUNK_T (T_DIM / S_CHUNKS)  // 64
#define NGJ 32                      // j2-groups of 256 pairs; grid = 16*32 = 512

// Scratch (device globals, no runtime alloc)
__device__ __half   g_h0[(size_t)M_DIM * H_DIM];
__device__ __half   g_h1[(size_t)M_DIM * H_DIM];
__device__ __half   g_G [(size_t)M_DIM * N_DIM];
__device__ __half   g_Wt[(size_t)L_DIM * N_DIM * K_DIM];
__device__ float    g_P [(size_t)S_CHUNKS * NCH];
__device__ float    g_Q [(size_t)S_CHUNKS * NCH];
__device__ unsigned g_flag[S_CHUNKS * NGJ];

// ---------------------------------------------------------------------------
// PTX helpers (sm_80-era only; compute_103 target rejects tcgen05)
// ---------------------------------------------------------------------------
__device__ __forceinline__ uint32_t smem_to_u32(const void* p) {
    uint32_t a;
    asm("{ .reg .u64 t; cvta.to.shared.u64 t, %1; cvt.u32.u64 %0, t; }" : "=r"(a) : "l"(p));
    return a;
}
#define CP_ASYNC16(sa, gp) \
    asm volatile("cp.async.cg.shared.global [%0], [%1], 16;" :: "r"(sa), "l"(gp))
#define CP_COMMIT() asm volatile("cp.async.commit_group;" ::: "memory")
#define CP_WAIT1()  asm volatile("cp.async.wait_group 1;" ::: "memory")
#define CP_WAIT0()  asm volatile("cp.async.wait_group 0;" ::: "memory")

#define LDSM_X4(r0, r1, r2, r3, addr) \
    asm volatile("ldmatrix.sync.aligned.m8n8.x4.shared.b16 {%0,%1,%2,%3}, [%4];" \
                 : "=r"(r0), "=r"(r1), "=r"(r2), "=r"(r3) : "r"(addr))

__device__ __forceinline__ void mma_f16(float& c0, float& c1, float& c2, float& c3,
                                        uint32_t a0, uint32_t a1, uint32_t a2, uint32_t a3,
                                        uint32_t b0, uint32_t b1) {
    asm volatile("mma.sync.aligned.m16n8k16.row.col.f32.f16.f16.f32 "
                 "{%0,%1,%2,%3}, {%4,%5,%6,%7}, {%8,%9}, {%0,%1,%2,%3};"
                 : "+f"(c0), "+f"(c1), "+f"(c2), "+f"(c3)
                 : "r"(a0), "r"(a1), "r"(a2), "r"(a3), "r"(b0), "r"(b1));
}

// ---------------------------------------------------------------------------
// FMA-only activations (avoid MUFU pipe)
// ---------------------------------------------------------------------------
__device__ __forceinline__ float rcp_fma(float d) {
    float r = __int_as_float(0x7EF127EAu - __float_as_int(d));
    r = r * (2.0f - d * r);
    r = r * (2.0f - d * r);
    r = r * (2.0f - d * r);
    return r;
}
__device__ __forceinline__ float tanh_fast(float x) {
    x = fminf(fmaxf(x, -7.90531110f), 7.90531110f);
    float x2 = x * x;
    float p = -2.76076847742355e-16f;
    p = fmaf(p, x2, 2.00018790482477e-13f);
    p = fmaf(p, x2, -8.60467152213735e-11f);
    p = fmaf(p, x2, 5.12229709037114e-08f);
    p = fmaf(p, x2, 1.48572235717979e-05f);
    p = fmaf(p, x2, 6.37261928875436e-04f);
    p = fmaf(p, x2, 4.89352455891786e-03f);
    float q = 1.19825839466702e-06f;
    q = fmaf(q, x2, 1.18534705686654e-04f);
    q = fmaf(q, x2, 2.26843463243900e-03f);
    q = fmaf(q, x2, 4.89352518554385e-03f);
    return (x * p) * rcp_fma(q);
}
__device__ __forceinline__ float sigmoid_fast(float x) {
    return fmaf(0.5f, tanh_fast(0.5f * x), 0.5f);
}

// ---------------------------------------------------------------------------
// Embedding gather -> fp16 h buffer
// ---------------------------------------------------------------------------
__global__ void embed_kernel(const int* __restrict__ x,
                             const float* __restrict__ emb,
                             __half* __restrict__ h)
{
    int idx = blockIdx.x * blockDim.x + threadIdx.x;
    int i   = idx * 4;
    int tb  = i >> 10;
    int hh  = i & (H_DIM - 1);
    int tok = x[tb];
    float4 v = *(const float4*)(emb + (size_t)tok * H_DIM + hh);
    __half2 lo = __floats2half2_rn(v.x, v.y);
    __half2 hi = __floats2half2_rn(v.z, v.w);
    uint2 pk = { *(uint32_t*)&lo, *(uint32_t*)&hi };
    *(uint2*)(h + i) = pk;
}

// ---------------------------------------------------------------------------
// W transpose + fp16 round:  Wt[l][n][k] = half(W[l][k][n])
// ---------------------------------------------------------------------------
__global__ void transpose_kernel(const float* __restrict__ W, __half* __restrict__ Wt)
{
    __shared__ float tile[32][33];
    int l  = blockIdx.z;
    int n0 = blockIdx.x * 32;
    int k0 = blockIdx.y * 32;
    int tx = threadIdx.x, ty = threadIdx.y;
    #pragma unroll
    for (int j = 0; j < 32; j += 8) {
        int k = k0 + ty + j, n = n0 + tx;
        tile[ty + j][tx] = W[((size_t)l * K_DIM + k) * N_DIM + n];
    }
    __syncthreads();
    #pragma unroll
    for (int j = 0; j < 32; j += 8) {
        int n = n0 + ty + j, k = k0 + tx;
        Wt[((size_t)l * N_DIM + n) * K_DIM + k] = __float2half_rn(tile[tx][ty + j]);
    }
}

// ---------------------------------------------------------------------------
// FP16 tensor-core GEMM (best-known): 128x128 CTA, 8 warps (2x4), ldmatrix,
// 3-stage cp.async pipeline, fragment ping-pong.
// ---------------------------------------------------------------------------
__global__ __launch_bounds__(256, 2)
void gemm_tc_kernel(const __half* __restrict__ A,
                    const __half* __restrict__ Bt,
                    const float* __restrict__ bias,
                    __half* __restrict__ C)
{
    extern __shared__ char smem[];

    const int tid = threadIdx.x;
    const int wid = tid >> 5;
    const int lid = tid & 31;
    const int g   = lid >> 2;
    const int t   = lid & 3;
    const int bm  = blockIdx.y * BM;
    const int bn  = blockIdx.x * BN;
    const int wm  = (wid >> 2) * WM;
    const int wn  = (wid & 3) * WN;

    const int l_row = tid >> 3;
    const int l_cir = tid & 7;
    const __half* Ag = A  + (size_t)(bm + l_row) * K_DIM + l_cir * 8;
    const __half* Bg = Bt + (size_t)(bn + l_row) * K_DIM + l_cir * 8;
    const uint32_t smem_base = smem_to_u32(smem);
    const uint32_t sAo = smem_base + l_row * ROWB + l_cir * 16;
    const uint32_t sBo = sAo + TILE_BYTES;

    const int r8 = lid & 7;
    const int q  = lid >> 3;
    uint32_t aoff[MT], boff[NT / 2];
    #pragma unroll
    for (int mt = 0; mt < MT; mt++)
        aoff[mt] = (uint32_t)((wm + mt * 16 + r8 + (q & 1) * 8) * ROWB + (q >> 1) * 16);
    #pragma unroll
    for (int p = 0; p < NT / 2; p++)
        boff[p] = (uint32_t)(TILE_BYTES + (wn + p * 16 + r8 + (q >> 1) * 8) * ROWB
                             + (q & 1) * 16);

    float acc[MT][NT][4];
    #pragma unroll
    for (int i = 0; i < MT; i++)
        #pragma unroll
        for (int j = 0; j < NT; j++)
            #pragma unroll
            for (int r = 0; r < 4; r++) acc[i][j][r] = 0.0f;

    #pragma unroll
    for (int p = 0; p < 2; p++) {
        const uint32_t soff = p * STAGE_BYTES;
        const __half* Ak = Ag + p * BK;
        const __half* Bk = Bg + p * BK;
        #pragma unroll
        for (int j = 0; j < 4; j++) {
            CP_ASYNC16(sAo + soff + j * 32 * ROWB, Ak + (size_t)(j * 32) * K_DIM);
            CP_ASYNC16(sBo + soff + j * 32 * ROWB, Bk + (size_t)(j * 32) * K_DIM);
        }
        CP_COMMIT();
    }

    int stg = 0, wst = 2;
    for (int i = 0; i < K_ITERS; i++) {
        if (i + 1 < K_ITERS) CP_WAIT1(); else CP_WAIT0();
        __syncthreads();

        if (i + 2 < K_ITERS) {
            const uint32_t soff = wst * STAGE_BYTES;
            const __half* Ak = Ag + (i + 2) * BK;
            const __half* Bk = Bg + (i + 2) * BK;
            #pragma unroll
            for (int j = 0; j < 4; j++) {
                CP_ASYNC16(sAo + soff + j * 32 * ROWB, Ak + (size_t)(j * 32) * K_DIM);
                CP_ASYNC16(sBo + soff + j * 32 * ROWB, Bk + (size_t)(j * 32) * K_DIM);
            }
            CP_COMMIT();
        }

        const uint32_t sbase = smem_base + stg * STAGE_BYTES;

        uint32_t af[2][MT][4], bf[2][NT][2];
        #pragma unroll
        for (int mt = 0; mt < MT; mt++)
            LDSM_X4(af[0][mt][0], af[0][mt][1], af[0][mt][2], af[0][mt][3],
                    sbase + aoff[mt]);
        #pragma unroll
        for (int p = 0; p < NT / 2; p++)
            LDSM_X4(bf[0][2*p][0], bf[0][2*p][1], bf[0][2*p+1][0], bf[0][2*p+1][1],
                    sbase + boff[p]);

        #pragma unroll
        for (int ks = 0; ks < 4; ks++) {
            const int cur = ks & 1;
            const int nxt = cur ^ 1;
            if (ks < 3) {
                const uint32_t kb = (ks + 1) * 32;
                #pragma unroll
                for (int mt = 0; mt < MT; mt++)
                    LDSM_X4(af[nxt][mt][0], af[nxt][mt][1], af[nxt][mt][2], af[nxt][mt][3],
                            sbase + aoff[mt] + kb);
                #pragma unroll
                for (int p = 0; p < NT / 2; p++)
                    LDSM_X4(bf[nxt][2*p][0], bf[nxt][2*p][1],
                            bf[nxt][2*p+1][0], bf[nxt][2*p+1][1],
                            sbase + boff[p] + kb);
            }
            #pragma unroll
            for (int mt = 0; mt < MT; mt++)
                #pragma unroll
                for (int nt = 0; nt < NT; nt++)
                    mma_f16(acc[mt][nt][0], acc[mt][nt][1],
                            acc[mt][nt][2], acc[mt][nt][3],
                            af[cur][mt][0], af[cur][mt][1],
                            af[cur][mt][2], af[cur][mt][3],
                            bf[cur][nt][0], bf[cur][nt][1]);
        }

        stg = (stg == 2) ? 0 : stg + 1;
        wst = (wst == 2) ? 0 : wst + 1;
    }

    // epilogue: hoisted bias, half2 stores
    float bw0[NT], bw1[NT];
    #pragma unroll
    for (int nt = 0; nt < NT; nt++) {
        const int col = bn + wn + nt * 8 + 2 * t;
        bw0[nt] = __ldg(&bias[col]);
        bw1[nt] = __ldg(&bias[col + 1]);
    }
    #pragma unroll
    for (int mt = 0; mt < MT; mt++) {
        const int row0 = bm + wm + mt * 16 + g;
        #pragma unroll
        for (int nt = 0; nt < NT; nt++) {
            const int col = bn + wn + nt * 8 + 2 * t;
            float2 v0, v1;
            if (col < H_DIM) {
                v0.x = tanh_fast(acc[mt][nt][0] + bw0[nt]);
                v0.y = tanh_fast(acc[mt][nt][1] + bw1[nt]);
                v1.x = tanh_fast(acc[mt][nt][2] + bw0[nt]);
                v1.y = tanh_fast(acc[mt][nt][3] + bw1[nt]);
            } else {
                v0.x = sigmoid_fast(acc[mt][nt][0] + bw0[nt]);
                v0.y = sigmoid_fast(acc[mt][nt][1] + bw1[nt]);
                v1.x = sigmoid_fast(acc[mt][nt][2] + bw0[nt]);
                v1.y = sigmoid_fast(acc[mt][nt][3] + bw1[nt]);
            }
            *(__half2*)&C[(size_t)row0 * N_DIM + col]       = __floats2half2_rn(v0.x, v0.y);
            *(__half2*)&C[(size_t)(row0 + 8) * N_DIM + col] = __floats2half2_rn(v1.x, v1.y);
        }
    }
}

// ---------------------------------------------------------------------------
// Single-pass chunked scan with decoupled lookback.
// s = bid>>5 (s-minor launch: chunk-0 blocks first), gj = bid&31.
// Phase A: local (P,Q), publish + flag. Phase B: spin on <=15 predecessor
// flags, compose init, rescan the SAME chunk (L2-hot) and emit o*c.
// Flags are zeroed by cudaMemsetAsync before each launch.
// ---------------------------------------------------------------------------
__global__ void scan_fused(const __half* __restrict__ G,
                           float* __restrict__ P, float* __restrict__ Q,
                           unsigned* __restrict__ flag,
                           float* __restrict__ outf, __half* __restrict__ outh,
                           int Tout, int write_half)
{
    const int bid = blockIdx.x;
    const int s   = bid >> 5;           // chunk index
    const int gj  = bid & (NGJ - 1);
    const int tid = threadIdx.x;
    const int j2  = gj * 256 + tid;     // channel-pair index
    const int b   = j2 >> 9;
    const int hh  = (j2 & 511) * 2;

    const __half* gz = G + ((size_t)(s * CHUNK_T) * B_DIM + b) * N_DIM + hh;

    // Phase A: local affine map of this chunk (init 0)
    float2 c = {0.0f, 0.0f}, p = {1.0f, 1.0f};
    #pragma unroll 8
    for (int t = 0; t < CHUNK_T; t++) {
        const __half* ptr = gz + (size_t)t * (B_DIM * N_DIM);
        float2 z = __half22float2(*(const __half2*)(ptr));
        float2 f = __half22float2(*(const __half2*)(ptr + H_DIM));
        c.x = fmaf(f.x, z.x - c.x, c.x);
        c.y = fmaf(f.y, z.y - c.y, c.y);
        p.x *= (1.0f - f.x);
        p.y *= (1.0f - f.y);
    }
    if (s < S_CHUNKS - 1) {             // last chunk has no successor
        *(float2*)&P[(size_t)s * NCH + 2 * j2] = p;
        *(float2*)&Q[(size_t)s * NCH + 2 * j2] = c;
        __threadfence();
        __syncthreads();
        if (tid == 0) atomicExch(&flag[bid], 1u);
    }

    // Phase B: wait for predecessors (same gj column, launched earlier)
    if (tid < s) {
        while (atomicAdd(&flag[tid * NGJ + gj], 0u) == 0u) __nanosleep(64);
    }
    __syncthreads();
    __threadfence();

    float2 ci = {0.0f, 0.0f};
    for (int ss = 0; ss < s; ss++) {
        float2 p2 = *(const float2*)&P[(size_t)ss * NCH + 2 * j2];
        float2 q2 = *(const float2*)&Q[(size_t)ss * NCH + 2 * j2];
        ci.x = fmaf(p2.x, ci.x, q2.x);
        ci.y = fmaf(p2.y, ci.y, q2.y);
    }

    // rescan with correct init (chunk data is L2-hot), emit o*c
    const size_t obase = ((size_t)(s * CHUNK_T) * B_DIM + b) * H_DIM + hh;
    const int tmax = Tout - s * CHUNK_T;
    #pragma unroll 8
    for (int t = 0; t < CHUNK_T; t++) {
        const __half* ptr = gz + (size_t)t * (B_DIM * N_DIM);
        float2 z = __half22float2(*(const __half2*)(ptr));
        float2 f = __half22float2(*(const __half2*)(ptr + H_DIM));
        float2 o = __half22float2(*(const __half2*)(ptr + 2 * H_DIM));
        ci.x = fmaf(f.x, z.x - ci.x, ci.x);
        ci.y = fmaf(f.y, z.y - ci.y, ci.y);
        if (t < tmax) {
            const size_t oi = obase + (size_t)t * (B_DIM * H_DIM);
            if (write_half)
                *(__half2*)&outh[oi] = __floats2half2_rn(o.x * ci.x, o.y * ci.y);
            else
                *(float2*)&outf[oi] = make_float2(o.x * ci.x, o.y * ci.y);
        }
    }
}

// ---------------------------------------------------------------------------
extern "C" void kernel_launch(void* const* d_in, const int* in_sizes, int n_in,
                              void* d_out, int out_size)
{
    const int*   x    = (const int*)  d_in[0];
    const float* emb  = (const float*)d_in[1];
    const float* W    = (const float*)d_in[2];
    const float* bias = (const float*)d_in[3];
    float* out = (float*)d_out;

    __half *h0, *h1, *Wt, *G;
    float *P, *Q;
    unsigned* flag;
    cudaGetSymbolAddress((void**)&h0, g_h0);
    cudaGetSymbolAddress((void**)&h1, g_h1);
    cudaGetSymbolAddress((void**)&G,  g_G);
    cudaGetSymbolAddress((void**)&Wt, g_Wt);
    cudaGetSymbolAddress((void**)&P,  g_P);
    cudaGetSymbolAddress((void**)&Q,  g_Q);
    cudaGetSymbolAddress((void**)&flag, g_flag);

    static bool attr_set = false;
    if (!attr_set) {
        cudaFuncSetAttribute(gemm_tc_kernel,
                             cudaFuncAttributeMaxDynamicSharedMemorySize, SM_TOTAL);
        attr_set = true;
    }

    embed_kernel<<<(M_DIM * H_DIM / 4) / 256, 256>>>(x, emb, h0);
    transpose_kernel<<<dim3(N_DIM / 32, K_DIM / 32, L_DIM), dim3(32, 8)>>>(W, Wt);

    dim3 ggrid(N_DIM / BN, M_DIM / BM);                 // (24, 128)
    const int sgrid = S_CHUNKS * NGJ;                   // 512 blocks x 256
    const size_t flag_bytes = S_CHUNKS * NGJ * sizeof(unsigned);

    gemm_tc_kernel<<<ggrid, 256, SM_TOTAL>>>(h0, Wt + 0 * (size_t)N_DIM * K_DIM,
                                             bias + 0 * N_DIM, G);
    cudaMemsetAsync(flag, 0, flag_bytes);
    scan_fused<<<sgrid, 256>>>(G, P, Q, flag, nullptr, h1, T_DIM, 1);

    gemm_tc_kernel<<<ggrid, 256, SM_TOTAL>>>(h1, Wt + 1 * (size_t)N_DIM * K_DIM,
                                             bias + 1 * N_DIM, G);
    cudaMemsetAsync(flag, 0, flag_bytes);
    scan_fused<<<sgrid, 256>>>(G, P, Q, flag, nullptr, h0, T_DIM, 1);

    gemm_tc_kernel<<<ggrid, 256, SM_TOTAL>>>(h0, Wt + 2 * (size_t)N_DIM * K_DIM,
                                             bias + 2 * N_DIM, G);
    cudaMemsetAsync(flag, 0, flag_bytes);
    scan_fused<<<sgrid, 256>>>(G, P, Q, flag, out, nullptr, T_DIM - 1, 0);
}

// round 13
// speedup vs baseline: 1.0169x; 1.0169x over previous
#include <cuda_runtime.h>
#include <cuda_fp16.h>
#include <cstdint>
#include <math.h>

// Problem dims
#define T_DIM 1024
#define B_DIM 16
#define H_DIM 1024
#define L_DIM 3
#define M_DIM (T_DIM * B_DIM)   // 16384
#define N_DIM (3 * H_DIM)       // 3072
#define K_DIM H_DIM             // 1024
#define NCH   (B_DIM * H_DIM)   // 16384 scan channels
#define NPAIR (NCH / 2)         // 8192 channel pairs

// GEMM tiling (fp16 operands, fp32 accum) — best-known shape (R7/R9)
#define BM 128
#define BN 128
#define BK 64
#define K_ITERS (K_DIM / BK)     // 16
#define WM 64
#define WN 32
#define MT (WM / 16)             // 4
#define NT (WN / 8)              // 4
#define ROWB 144                 // bytes per SMEM row (72 halves, padded)
#define TILE_BYTES (128 * ROWB)
#define STAGE_BYTES (2 * TILE_BYTES)
#define STAGES 3
#define SM_TOTAL (STAGES * STAGE_BYTES)    // 110592

// Scan chunking (widened for latency hiding)
#define S_CHUNKS 32
#define CHUNK_T (T_DIM / S_CHUNKS)  // 32

// Scratch (device globals, no runtime alloc)
__device__ __half g_h0[(size_t)M_DIM * H_DIM];
__device__ __half g_h1[(size_t)M_DIM * H_DIM];
__device__ __half g_G [(size_t)M_DIM * N_DIM];
__device__ __half g_Wt[(size_t)L_DIM * N_DIM * K_DIM];
__device__ float  g_P [(size_t)S_CHUNKS * NCH];
__device__ float  g_Q [(size_t)S_CHUNKS * NCH];

// ---------------------------------------------------------------------------
// PTX helpers (sm_80-era only; compute_103 target rejects tcgen05)
// ---------------------------------------------------------------------------
__device__ __forceinline__ uint32_t smem_to_u32(const void* p) {
    uint32_t a;
    asm("{ .reg .u64 t; cvta.to.shared.u64 t, %1; cvt.u32.u64 %0, t; }" : "=r"(a) : "l"(p));
    return a;
}
#define CP_ASYNC16(sa, gp) \
    asm volatile("cp.async.cg.shared.global [%0], [%1], 16;" :: "r"(sa), "l"(gp))
#define CP_COMMIT() asm volatile("cp.async.commit_group;" ::: "memory")
#define CP_WAIT1()  asm volatile("cp.async.wait_group 1;" ::: "memory")
#define CP_WAIT0()  asm volatile("cp.async.wait_group 0;" ::: "memory")

#define LDSM_X4(r0, r1, r2, r3, addr) \
    asm volatile("ldmatrix.sync.aligned.m8n8.x4.shared.b16 {%0,%1,%2,%3}, [%4];" \
                 : "=r"(r0), "=r"(r1), "=r"(r2), "=r"(r3) : "r"(addr))

__device__ __forceinline__ void mma_f16(float& c0, float& c1, float& c2, float& c3,
                                        uint32_t a0, uint32_t a1, uint32_t a2, uint32_t a3,
                                        uint32_t b0, uint32_t b1) {
    asm volatile("mma.sync.aligned.m16n8k16.row.col.f32.f16.f16.f32 "
                 "{%0,%1,%2,%3}, {%4,%5,%6,%7}, {%8,%9}, {%0,%1,%2,%3};"
                 : "+f"(c0), "+f"(c1), "+f"(c2), "+f"(c3)
                 : "r"(a0), "r"(a1), "r"(a2), "r"(a3), "r"(b0), "r"(b1));
}

// ---------------------------------------------------------------------------
// FMA-only activations (avoid MUFU pipe)
// ---------------------------------------------------------------------------
__device__ __forceinline__ float rcp_fma(float d) {
    float r = __int_as_float(0x7EF127EAu - __float_as_int(d));
    r = r * (2.0f - d * r);
    r = r * (2.0f - d * r);
    r = r * (2.0f - d * r);
    return r;
}
__device__ __forceinline__ float tanh_fast(float x) {
    x = fminf(fmaxf(x, -7.90531110f), 7.90531110f);
    float x2 = x * x;
    float p = -2.76076847742355e-16f;
    p = fmaf(p, x2, 2.00018790482477e-13f);
    p = fmaf(p, x2, -8.60467152213735e-11f);
    p = fmaf(p, x2, 5.12229709037114e-08f);
    p = fmaf(p, x2, 1.48572235717979e-05f);
    p = fmaf(p, x2, 6.37261928875436e-04f);
    p = fmaf(p, x2, 4.89352455891786e-03f);
    float q = 1.19825839466702e-06f;
    q = fmaf(q, x2, 1.18534705686654e-04f);
    q = fmaf(q, x2, 2.26843463243900e-03f);
    q = fmaf(q, x2, 4.89352518554385e-03f);
    return (x * p) * rcp_fma(q);
}
__device__ __forceinline__ float sigmoid_fast(float x) {
    return fmaf(0.5f, tanh_fast(0.5f * x), 0.5f);
}

// ---------------------------------------------------------------------------
// Embedding gather -> fp16 h buffer
// ---------------------------------------------------------------------------
__global__ void embed_kernel(const int* __restrict__ x,
                             const float* __restrict__ emb,
                             __half* __restrict__ h)
{
    int idx = blockIdx.x * blockDim.x + threadIdx.x;
    int i   = idx * 4;
    int tb  = i >> 10;
    int hh  = i & (H_DIM - 1);
    int tok = x[tb];
    float4 v = *(const float4*)(emb + (size_t)tok * H_DIM + hh);
    __half2 lo = __floats2half2_rn(v.x, v.y);
    __half2 hi = __floats2half2_rn(v.z, v.w);
    uint2 pk = { *(uint32_t*)&lo, *(uint32_t*)&hi };
    *(uint2*)(h + i) = pk;
}

// ---------------------------------------------------------------------------
// W transpose + fp16 round:  Wt[l][n][k] = half(W[l][k][n])
// ---------------------------------------------------------------------------
__global__ void transpose_kernel(const float* __restrict__ W, __half* __restrict__ Wt)
{
    __shared__ float tile[32][33];
    int l  = blockIdx.z;
    int n0 = blockIdx.x * 32;
    int k0 = blockIdx.y * 32;
    int tx = threadIdx.x, ty = threadIdx.y;
    #pragma unroll
    for (int j = 0; j < 32; j += 8) {
        int k = k0 + ty + j, n = n0 + tx;
        tile[ty + j][tx] = W[((size_t)l * K_DIM + k) * N_DIM + n];
    }
    __syncthreads();
    #pragma unroll
    for (int j = 0; j < 32; j += 8) {
        int n = n0 + ty + j, k = k0 + tx;
        Wt[((size_t)l * N_DIM + n) * K_DIM + k] = __float2half_rn(tile[tx][ty + j]);
    }
}

// ---------------------------------------------------------------------------
// FP16 tensor-core GEMM (best-known): 128x128 CTA, 8 warps (2x4), ldmatrix,
// 3-stage cp.async pipeline, fragment ping-pong.
// ---------------------------------------------------------------------------
__global__ __launch_bounds__(256, 2)
void gemm_tc_kernel(const __half* __restrict__ A,
                    const __half* __restrict__ Bt,
                    const float* __restrict__ bias,
                    __half* __restrict__ C)
{
    extern __shared__ char smem[];

    const int tid = threadIdx.x;
    const int wid = tid >> 5;
    const int lid = tid & 31;
    const int g   = lid >> 2;
    const int t   = lid & 3;
    const int bm  = blockIdx.y * BM;
    const int bn  = blockIdx.x * BN;
    const int wm  = (wid >> 2) * WM;
    const int wn  = (wid & 3) * WN;

    const int l_row = tid >> 3;
    const int l_cir = tid & 7;
    const __half* Ag = A  + (size_t)(bm + l_row) * K_DIM + l_cir * 8;
    const __half* Bg = Bt + (size_t)(bn + l_row) * K_DIM + l_cir * 8;
    const uint32_t smem_base = smem_to_u32(smem);
    const uint32_t sAo = smem_base + l_row * ROWB + l_cir * 16;
    const uint32_t sBo = sAo + TILE_BYTES;

    const int r8 = lid & 7;
    const int q  = lid >> 3;
    uint32_t aoff[MT], boff[NT / 2];
    #pragma unroll
    for (int mt = 0; mt < MT; mt++)
        aoff[mt] = (uint32_t)((wm + mt * 16 + r8 + (q & 1) * 8) * ROWB + (q >> 1) * 16);
    #pragma unroll
    for (int p = 0; p < NT / 2; p++)
        boff[p] = (uint32_t)(TILE_BYTES + (wn + p * 16 + r8 + (q >> 1) * 8) * ROWB
                             + (q & 1) * 16);

    float acc[MT][NT][4];
    #pragma unroll
    for (int i = 0; i < MT; i++)
        #pragma unroll
        for (int j = 0; j < NT; j++)
            #pragma unroll
            for (int r = 0; r < 4; r++) acc[i][j][r] = 0.0f;

    #pragma unroll
    for (int p = 0; p < 2; p++) {
        const uint32_t soff = p * STAGE_BYTES;
        const __half* Ak = Ag + p * BK;
        const __half* Bk = Bg + p * BK;
        #pragma unroll
        for (int j = 0; j < 4; j++) {
            CP_ASYNC16(sAo + soff + j * 32 * ROWB, Ak + (size_t)(j * 32) * K_DIM);
            CP_ASYNC16(sBo + soff + j * 32 * ROWB, Bk + (size_t)(j * 32) * K_DIM);
        }
        CP_COMMIT();
    }

    int stg = 0, wst = 2;
    for (int i = 0; i < K_ITERS; i++) {
        if (i + 1 < K_ITERS) CP_WAIT1(); else CP_WAIT0();
        __syncthreads();

        if (i + 2 < K_ITERS) {
            const uint32_t soff = wst * STAGE_BYTES;
            const __half* Ak = Ag + (i + 2) * BK;
            const __half* Bk = Bg + (i + 2) * BK;
            #pragma unroll
            for (int j = 0; j < 4; j++) {
                CP_ASYNC16(sAo + soff + j * 32 * ROWB, Ak + (size_t)(j * 32) * K_DIM);
                CP_ASYNC16(sBo + soff + j * 32 * ROWB, Bk + (size_t)(j * 32) * K_DIM);
            }
            CP_COMMIT();
        }

        const uint32_t sbase = smem_base + stg * STAGE_BYTES;

        uint32_t af[2][MT][4], bf[2][NT][2];
        #pragma unroll
        for (int mt = 0; mt < MT; mt++)
            LDSM_X4(af[0][mt][0], af[0][mt][1], af[0][mt][2], af[0][mt][3],
                    sbase + aoff[mt]);
        #pragma unroll
        for (int p = 0; p < NT / 2; p++)
            LDSM_X4(bf[0][2*p][0], bf[0][2*p][1], bf[0][2*p+1][0], bf[0][2*p+1][1],
                    sbase + boff[p]);

        #pragma unroll
        for (int ks = 0; ks < 4; ks++) {
            const int cur = ks & 1;
            const int nxt = cur ^ 1;
            if (ks < 3) {
                const uint32_t kb = (ks + 1) * 32;
                #pragma unroll
                for (int mt = 0; mt < MT; mt++)
                    LDSM_X4(af[nxt][mt][0], af[nxt][mt][1], af[nxt][mt][2], af[nxt][mt][3],
                            sbase + aoff[mt] + kb);
                #pragma unroll
                for (int p = 0; p < NT / 2; p++)
                    LDSM_X4(bf[nxt][2*p][0], bf[nxt][2*p][1],
                            bf[nxt][2*p+1][0], bf[nxt][2*p+1][1],
                            sbase + boff[p] + kb);
            }
            #pragma unroll
            for (int mt = 0; mt < MT; mt++)
                #pragma unroll
                for (int nt = 0; nt < NT; nt++)
                    mma_f16(acc[mt][nt][0], acc[mt][nt][1],
                            acc[mt][nt][2], acc[mt][nt][3],
                            af[cur][mt][0], af[cur][mt][1],
                            af[cur][mt][2], af[cur][mt][3],
                            bf[cur][nt][0], bf[cur][nt][1]);
        }

        stg = (stg == 2) ? 0 : stg + 1;
        wst = (wst == 2) ? 0 : wst + 1;
    }

    // epilogue: hoisted bias, half2 stores
    float bw0[NT], bw1[NT];
    #pragma unroll
    for (int nt = 0; nt < NT; nt++) {
        const int col = bn + wn + nt * 8 + 2 * t;
        bw0[nt] = __ldg(&bias[col]);
        bw1[nt] = __ldg(&bias[col + 1]);
    }
    #pragma unroll
    for (int mt = 0; mt < MT; mt++) {
        const int row0 = bm + wm + mt * 16 + g;
        #pragma unroll
        for (int nt = 0; nt < NT; nt++) {
            const int col = bn + wn + nt * 8 + 2 * t;
            float2 v0, v1;
            if (col < H_DIM) {
                v0.x = tanh_fast(acc[mt][nt][0] + bw0[nt]);
                v0.y = tanh_fast(acc[mt][nt][1] + bw1[nt]);
                v1.x = tanh_fast(acc[mt][nt][2] + bw0[nt]);
                v1.y = tanh_fast(acc[mt][nt][3] + bw1[nt]);
            } else {
                v0.x = sigmoid_fast(acc[mt][nt][0] + bw0[nt]);
                v0.y = sigmoid_fast(acc[mt][nt][1] + bw1[nt]);
                v1.x = sigmoid_fast(acc[mt][nt][2] + bw0[nt]);
                v1.y = sigmoid_fast(acc[mt][nt][3] + bw1[nt]);
            }
            *(__half2*)&C[(size_t)row0 * N_DIM + col]       = __floats2half2_rn(v0.x, v0.y);
            *(__half2*)&C[(size_t)(row0 + 8) * N_DIM + col] = __floats2half2_rn(v1.x, v1.y);
        }
    }
}

// ---------------------------------------------------------------------------
// Chunked-parallel forget-mult scan over fp16 gates, half2 channel pairs.
// Two-pass (proven); S_CHUNKS=32 for more latency-hiding parallelism.
// pass1: per-chunk affine map (P = prod(1-f), Q = chunk scan from 0).
// ---------------------------------------------------------------------------
__global__ void scan_pass1(const __half* __restrict__ G,
                           float* __restrict__ P, float* __restrict__ Q)
{
    const int id = blockIdx.x * blockDim.x + threadIdx.x;   // 0 .. S*NPAIR-1
    const int j2 = id & (NPAIR - 1);
    const int s  = id >> 13;
    const int b  = j2 >> 9;
    const int hh = (j2 & 511) * 2;

    if (s == S_CHUNKS - 1) return;      // last chunk's map is never consumed

    const __half* gz = G + ((size_t)(s * CHUNK_T) * B_DIM + b) * N_DIM + hh;
    float2 c = {0.0f, 0.0f}, p = {1.0f, 1.0f};
    #pragma unroll 8
    for (int t = 0; t < CHUNK_T; t++) {
        const __half* ptr = gz + (size_t)t * (B_DIM * N_DIM);
        float2 z = __half22float2(*(const __half2*)(ptr));
        float2 f = __half22float2(*(const __half2*)(ptr + H_DIM));
        c.x = fmaf(f.x, z.x - c.x, c.x);
        c.y = fmaf(f.y, z.y - c.y, c.y);
        p.x *= (1.0f - f.x);
        p.y *= (1.0f - f.y);
    }
    *(float2*)&P[(size_t)s * NCH + 2 * j2] = p;
    *(float2*)&Q[(size_t)s * NCH + 2 * j2] = c;
}

// pass2: combine predecessor maps, rescan, emit o*c
__global__ void scan_pass2(const __half* __restrict__ G,
                           const float* __restrict__ P, const float* __restrict__ Q,
                           float* __restrict__ outf, __half* __restrict__ outh,
                           int Tout, int write_half)
{
    const int id = blockIdx.x * blockDim.x + threadIdx.x;
    const int j2 = id & (NPAIR - 1);
    const int s  = id >> 13;
    const int b  = j2 >> 9;
    const int hh = (j2 & 511) * 2;

    float2 c = {0.0f, 0.0f};
    for (int ss = 0; ss < s; ss++) {
        float2 p2 = *(const float2*)&P[(size_t)ss * NCH + 2 * j2];
        float2 q2 = *(const float2*)&Q[(size_t)ss * NCH + 2 * j2];
        c.x = fmaf(p2.x, c.x, q2.x);
        c.y = fmaf(p2.y, c.y, q2.y);
    }

    const __half* gz = G + ((size_t)(s * CHUNK_T) * B_DIM + b) * N_DIM + hh;
    const size_t obase = ((size_t)(s * CHUNK_T) * B_DIM + b) * H_DIM + hh;
    const int tmax = Tout - s * CHUNK_T;
    #pragma unroll 8
    for (int t = 0; t < CHUNK_T; t++) {
        const __half* ptr = gz + (size_t)t * (B_DIM * N_DIM);
        float2 z = __half22float2(*(const __half2*)(ptr));
        float2 f = __half22float2(*(const __half2*)(ptr + H_DIM));
        float2 o = __half22float2(*(const __half2*)(ptr + 2 * H_DIM));
        c.x = fmaf(f.x, z.x - c.x, c.x);
        c.y = fmaf(f.y, z.y - c.y, c.y);
        if (t < tmax) {
            const size_t oi = obase + (size_t)t * (B_DIM * H_DIM);
            if (write_half)
                *(__half2*)&outh[oi] = __floats2half2_rn(o.x * c.x, o.y * c.y);
            else
                *(float2*)&outf[oi] = make_float2(o.x * c.x, o.y * c.y);
        }
    }
}

// ---------------------------------------------------------------------------
extern "C" void kernel_launch(void* const* d_in, const int* in_sizes, int n_in,
                              void* d_out, int out_size)
{
    const int*   x    = (const int*)  d_in[0];
    const float* emb  = (const float*)d_in[1];
    const float* W    = (const float*)d_in[2];
    const float* bias = (const float*)d_in[3];
    float* out = (float*)d_out;

    __half *h0, *h1, *Wt, *G;
    float *P, *Q;
    cudaGetSymbolAddress((void**)&h0, g_h0);
    cudaGetSymbolAddress((void**)&h1, g_h1);
    cudaGetSymbolAddress((void**)&G,  g_G);
    cudaGetSymbolAddress((void**)&Wt, g_Wt);
    cudaGetSymbolAddress((void**)&P,  g_P);
    cudaGetSymbolAddress((void**)&Q,  g_Q);

    static bool attr_set = false;
    if (!attr_set) {
        cudaFuncSetAttribute(gemm_tc_kernel,
                             cudaFuncAttributeMaxDynamicSharedMemorySize, SM_TOTAL);
        attr_set = true;
    }

    embed_kernel<<<(M_DIM * H_DIM / 4) / 256, 256>>>(x, emb, h0);
    transpose_kernel<<<dim3(N_DIM / 32, K_DIM / 32, L_DIM), dim3(32, 8)>>>(W, Wt);

    dim3 ggrid(N_DIM / BN, M_DIM / BM);                 // (24, 128)
    const int sgrid = (S_CHUNKS * NPAIR) / 256;         // 1024 blocks x 256

    gemm_tc_kernel<<<ggrid, 256, SM_TOTAL>>>(h0, Wt + 0 * (size_t)N_DIM * K_DIM,
                                             bias + 0 * N_DIM, G);
    scan_pass1<<<sgrid, 256>>>(G, P, Q);
    scan_pass2<<<sgrid, 256>>>(G, P, Q, nullptr, h1, T_DIM, 1);

    gemm_tc_kernel<<<ggrid, 256, SM_TOTAL>>>(h1, Wt + 1 * (size_t)N_DIM * K_DIM,
                                             bias + 1 * N_DIM, G);
    scan_pass1<<<sgrid, 256>>>(G, P, Q);
    scan_pass2<<<sgrid, 256>>>(G, P, Q, nullptr, h0, T_DIM, 1);

    gemm_tc_kernel<<<ggrid, 256, SM_TOTAL>>>(h0, Wt + 2 * (size_t)N_DIM * K_DIM,
                                             bias + 2 * N_DIM, G);
    scan_pass1<<<sgrid, 256>>>(G, P, Q);
    scan_pass2<<<sgrid, 256>>>(G, P, Q, out, nullptr, T_DIM - 1, 0);
}

// round 14
// speedup vs baseline: 1.0235x; 1.0064x over previous
#include <cuda_runtime.h>
#include <cuda_fp16.h>
#include <cstdint>
#include <math.h>

// Problem dims
#define T_DIM 1024
#define B_DIM 16
#define H_DIM 1024
#define L_DIM 3
#define M_DIM (T_DIM * B_DIM)   // 16384
#define N_DIM (3 * H_DIM)       // 3072
#define K_DIM H_DIM             // 1024
#define NCH   (B_DIM * H_DIM)   // 16384 scan channels
#define NPAIR (NCH / 2)         // 8192 channel pairs

// GEMM tiling (fp16 operands, fp32 accum) — best-known shape (R7/R9)
#define BM 128
#define BN 128
#define BK 64
#define K_ITERS (K_DIM / BK)     // 16
#define WM 64
#define WN 32
#define MT (WM / 16)             // 4
#define NT (WN / 8)              // 4
#define ROWB 144                 // bytes per SMEM row (72 halves, padded)
#define TILE_BYTES (128 * ROWB)
#define STAGE_BYTES (2 * TILE_BYTES)
#define STAGES 3
#define SM_TOTAL (STAGES * STAGE_BYTES)    // 110592

// Scan chunking (best-measured: 16)
#define S_CHUNKS 16
#define CHUNK_T (T_DIM / S_CHUNKS)  // 64

// Scratch (device globals, no runtime alloc)
__device__ __half g_h0[(size_t)M_DIM * H_DIM];
__device__ __half g_h1[(size_t)M_DIM * H_DIM];
__device__ __half g_G [(size_t)M_DIM * N_DIM];
__device__ __half g_Wt[(size_t)L_DIM * N_DIM * K_DIM];
__device__ float  g_P [(size_t)S_CHUNKS * NCH];
__device__ float  g_Q [(size_t)S_CHUNKS * NCH];

// ---------------------------------------------------------------------------
// PTX helpers (sm_80-era only; compute_103 target rejects tcgen05)
// ---------------------------------------------------------------------------
__device__ __forceinline__ uint32_t smem_to_u32(const void* p) {
    uint32_t a;
    asm("{ .reg .u64 t; cvta.to.shared.u64 t, %1; cvt.u32.u64 %0, t; }" : "=r"(a) : "l"(p));
    return a;
}
#define CP_ASYNC16(sa, gp) \
    asm volatile("cp.async.cg.shared.global [%0], [%1], 16;" :: "r"(sa), "l"(gp))
#define CP_COMMIT() asm volatile("cp.async.commit_group;" ::: "memory")
#define CP_WAIT1()  asm volatile("cp.async.wait_group 1;" ::: "memory")
#define CP_WAIT0()  asm volatile("cp.async.wait_group 0;" ::: "memory")

#define LDSM_X4(r0, r1, r2, r3, addr) \
    asm volatile("ldmatrix.sync.aligned.m8n8.x4.shared.b16 {%0,%1,%2,%3}, [%4];" \
                 : "=r"(r0), "=r"(r1), "=r"(r2), "=r"(r3) : "r"(addr))

__device__ __forceinline__ void mma_f16(float& c0, float& c1, float& c2, float& c3,
                                        uint32_t a0, uint32_t a1, uint32_t a2, uint32_t a3,
                                        uint32_t b0, uint32_t b1) {
    asm volatile("mma.sync.aligned.m16n8k16.row.col.f32.f16.f16.f32 "
                 "{%0,%1,%2,%3}, {%4,%5,%6,%7}, {%8,%9}, {%0,%1,%2,%3};"
                 : "+f"(c0), "+f"(c1), "+f"(c2), "+f"(c3)
                 : "r"(a0), "r"(a1), "r"(a2), "r"(a3), "r"(b0), "r"(b1));
}

// ---------------------------------------------------------------------------
// FMA-only activations (avoid MUFU pipe)
// ---------------------------------------------------------------------------
__device__ __forceinline__ float rcp_fma(float d) {
    float r = __int_as_float(0x7EF127EAu - __float_as_int(d));
    r = r * (2.0f - d * r);
    r = r * (2.0f - d * r);
    r = r * (2.0f - d * r);
    return r;
}
__device__ __forceinline__ float tanh_fast(float x) {
    x = fminf(fmaxf(x, -7.90531110f), 7.90531110f);
    float x2 = x * x;
    float p = -2.76076847742355e-16f;
    p = fmaf(p, x2, 2.00018790482477e-13f);
    p = fmaf(p, x2, -8.60467152213735e-11f);
    p = fmaf(p, x2, 5.12229709037114e-08f);
    p = fmaf(p, x2, 1.48572235717979e-05f);
    p = fmaf(p, x2, 6.37261928875436e-04f);
    p = fmaf(p, x2, 4.89352455891786e-03f);
    float q = 1.19825839466702e-06f;
    q = fmaf(q, x2, 1.18534705686654e-04f);
    q = fmaf(q, x2, 2.26843463243900e-03f);
    q = fmaf(q, x2, 4.89352518554385e-03f);
    return (x * p) * rcp_fma(q);
}
__device__ __forceinline__ float sigmoid_fast(float x) {
    return fmaf(0.5f, tanh_fast(0.5f * x), 0.5f);
}

// ---------------------------------------------------------------------------
// Embedding gather -> fp16 h buffer
// ---------------------------------------------------------------------------
__global__ void embed_kernel(const int* __restrict__ x,
                             const float* __restrict__ emb,
                             __half* __restrict__ h)
{
    int idx = blockIdx.x * blockDim.x + threadIdx.x;
    int i   = idx * 4;
    int tb  = i >> 10;
    int hh  = i & (H_DIM - 1);
    int tok = x[tb];
    float4 v = *(const float4*)(emb + (size_t)tok * H_DIM + hh);
    __half2 lo = __floats2half2_rn(v.x, v.y);
    __half2 hi = __floats2half2_rn(v.z, v.w);
    uint2 pk = { *(uint32_t*)&lo, *(uint32_t*)&hi };
    *(uint2*)(h + i) = pk;
}

// ---------------------------------------------------------------------------
// W transpose + fp16 round:  Wt[l][n][k] = half(W[l][k][n])
// ---------------------------------------------------------------------------
__global__ void transpose_kernel(const float* __restrict__ W, __half* __restrict__ Wt)
{
    __shared__ float tile[32][33];
    int l  = blockIdx.z;
    int n0 = blockIdx.x * 32;
    int k0 = blockIdx.y * 32;
    int tx = threadIdx.x, ty = threadIdx.y;
    #pragma unroll
    for (int j = 0; j < 32; j += 8) {
        int k = k0 + ty + j, n = n0 + tx;
        tile[ty + j][tx] = W[((size_t)l * K_DIM + k) * N_DIM + n];
    }
    __syncthreads();
    #pragma unroll
    for (int j = 0; j < 32; j += 8) {
        int n = n0 + ty + j, k = k0 + tx;
        Wt[((size_t)l * N_DIM + n) * K_DIM + k] = __float2half_rn(tile[tx][ty + j]);
    }
}

// ---------------------------------------------------------------------------
// FP16 tensor-core GEMM (best-known): 128x128 CTA, 8 warps (2x4), ldmatrix,
// 3-stage cp.async pipeline, fragment ping-pong.
// ---------------------------------------------------------------------------
__global__ __launch_bounds__(256, 2)
void gemm_tc_kernel(const __half* __restrict__ A,
                    const __half* __restrict__ Bt,
                    const float* __restrict__ bias,
                    __half* __restrict__ C)
{
    extern __shared__ char smem[];

    const int tid = threadIdx.x;
    const int wid = tid >> 5;
    const int lid = tid & 31;
    const int g   = lid >> 2;
    const int t   = lid & 3;
    const int bm  = blockIdx.y * BM;
    const int bn  = blockIdx.x * BN;
    const int wm  = (wid >> 2) * WM;
    const int wn  = (wid & 3) * WN;

    const int l_row = tid >> 3;
    const int l_cir = tid & 7;
    const __half* Ag = A  + (size_t)(bm + l_row) * K_DIM + l_cir * 8;
    const __half* Bg = Bt + (size_t)(bn + l_row) * K_DIM + l_cir * 8;
    const uint32_t smem_base = smem_to_u32(smem);
    const uint32_t sAo = smem_base + l_row * ROWB + l_cir * 16;
    const uint32_t sBo = sAo + TILE_BYTES;

    const int r8 = lid & 7;
    const int q  = lid >> 3;
    uint32_t aoff[MT], boff[NT / 2];
    #pragma unroll
    for (int mt = 0; mt < MT; mt++)
        aoff[mt] = (uint32_t)((wm + mt * 16 + r8 + (q & 1) * 8) * ROWB + (q >> 1) * 16);
    #pragma unroll
    for (int p = 0; p < NT / 2; p++)
        boff[p] = (uint32_t)(TILE_BYTES + (wn + p * 16 + r8 + (q >> 1) * 8) * ROWB
                             + (q & 1) * 16);

    float acc[MT][NT][4];
    #pragma unroll
    for (int i = 0; i < MT; i++)
        #pragma unroll
        for (int j = 0; j < NT; j++)
            #pragma unroll
            for (int r = 0; r < 4; r++) acc[i][j][r] = 0.0f;

    #pragma unroll
    for (int p = 0; p < 2; p++) {
        const uint32_t soff = p * STAGE_BYTES;
        const __half* Ak = Ag + p * BK;
        const __half* Bk = Bg + p * BK;
        #pragma unroll
        for (int j = 0; j < 4; j++) {
            CP_ASYNC16(sAo + soff + j * 32 * ROWB, Ak + (size_t)(j * 32) * K_DIM);
            CP_ASYNC16(sBo + soff + j * 32 * ROWB, Bk + (size_t)(j * 32) * K_DIM);
        }
        CP_COMMIT();
    }

    int stg = 0, wst = 2;
    for (int i = 0; i < K_ITERS; i++) {
        if (i + 1 < K_ITERS) CP_WAIT1(); else CP_WAIT0();
        __syncthreads();

        if (i + 2 < K_ITERS) {
            const uint32_t soff = wst * STAGE_BYTES;
            const __half* Ak = Ag + (i + 2) * BK;
            const __half* Bk = Bg + (i + 2) * BK;
            #pragma unroll
            for (int j = 0; j < 4; j++) {
                CP_ASYNC16(sAo + soff + j * 32 * ROWB, Ak + (size_t)(j * 32) * K_DIM);
                CP_ASYNC16(sBo + soff + j * 32 * ROWB, Bk + (size_t)(j * 32) * K_DIM);
            }
            CP_COMMIT();
        }

        const uint32_t sbase = smem_base + stg * STAGE_BYTES;

        uint32_t af[2][MT][4], bf[2][NT][2];
        #pragma unroll
        for (int mt = 0; mt < MT; mt++)
            LDSM_X4(af[0][mt][0], af[0][mt][1], af[0][mt][2], af[0][mt][3],
                    sbase + aoff[mt]);
        #pragma unroll
        for (int p = 0; p < NT / 2; p++)
            LDSM_X4(bf[0][2*p][0], bf[0][2*p][1], bf[0][2*p+1][0], bf[0][2*p+1][1],
                    sbase + boff[p]);

        #pragma unroll
        for (int ks = 0; ks < 4; ks++) {
            const int cur = ks & 1;
            const int nxt = cur ^ 1;
            if (ks < 3) {
                const uint32_t kb = (ks + 1) * 32;
                #pragma unroll
                for (int mt = 0; mt < MT; mt++)
                    LDSM_X4(af[nxt][mt][0], af[nxt][mt][1], af[nxt][mt][2], af[nxt][mt][3],
                            sbase + aoff[mt] + kb);
                #pragma unroll
                for (int p = 0; p < NT / 2; p++)
                    LDSM_X4(bf[nxt][2*p][0], bf[nxt][2*p][1],
                            bf[nxt][2*p+1][0], bf[nxt][2*p+1][1],
                            sbase + boff[p] + kb);
            }
            #pragma unroll
            for (int mt = 0; mt < MT; mt++)
                #pragma unroll
                for (int nt = 0; nt < NT; nt++)
                    mma_f16(acc[mt][nt][0], acc[mt][nt][1],
                            acc[mt][nt][2], acc[mt][nt][3],
                            af[cur][mt][0], af[cur][mt][1],
                            af[cur][mt][2], af[cur][mt][3],
                            bf[cur][nt][0], bf[cur][nt][1]);
        }

        stg = (stg == 2) ? 0 : stg + 1;
        wst = (wst == 2) ? 0 : wst + 1;
    }

    // epilogue: hoisted bias, half2 stores
    float bw0[NT], bw1[NT];
    #pragma unroll
    for (int nt = 0; nt < NT; nt++) {
        const int col = bn + wn + nt * 8 + 2 * t;
        bw0[nt] = __ldg(&bias[col]);
        bw1[nt] = __ldg(&bias[col + 1]);
    }
    #pragma unroll
    for (int mt = 0; mt < MT; mt++) {
        const int row0 = bm + wm + mt * 16 + g;
        #pragma unroll
        for (int nt = 0; nt < NT; nt++) {
            const int col = bn + wn + nt * 8 + 2 * t;
            float2 v0, v1;
            if (col < H_DIM) {
                v0.x = tanh_fast(acc[mt][nt][0] + bw0[nt]);
                v0.y = tanh_fast(acc[mt][nt][1] + bw1[nt]);
                v1.x = tanh_fast(acc[mt][nt][2] + bw0[nt]);
                v1.y = tanh_fast(acc[mt][nt][3] + bw1[nt]);
            } else {
                v0.x = sigmoid_fast(acc[mt][nt][0] + bw0[nt]);
                v0.y = sigmoid_fast(acc[mt][nt][1] + bw1[nt]);
                v1.x = sigmoid_fast(acc[mt][nt][2] + bw0[nt]);
                v1.y = sigmoid_fast(acc[mt][nt][3] + bw1[nt]);
            }
            *(__half2*)&C[(size_t)row0 * N_DIM + col]       = __floats2half2_rn(v0.x, v0.y);
            *(__half2*)&C[(size_t)(row0 + 8) * N_DIM + col] = __floats2half2_rn(v1.x, v1.y);
        }
    }
}

// ---------------------------------------------------------------------------
// Chunked-parallel forget-mult scan over fp16 gates, half2 channel pairs.
// Two-pass; S_CHUNKS=16 (best measured). pass1 skips the last chunk (its
// affine map has no consumer).
// ---------------------------------------------------------------------------
__global__ void scan_pass1(const __half* __restrict__ G,
                           float* __restrict__ P, float* __restrict__ Q)
{
    const int id = blockIdx.x * blockDim.x + threadIdx.x;   // 0 .. (S-1)*NPAIR-1
    const int j2 = id & (NPAIR - 1);
    const int s  = id >> 13;
    const int b  = j2 >> 9;
    const int hh = (j2 & 511) * 2;
    const __half* gz = G + ((size_t)(s * CHUNK_T) * B_DIM + b) * N_DIM + hh;

    float2 c = {0.0f, 0.0f}, p = {1.0f, 1.0f};
    #pragma unroll 8
    for (int t = 0; t < CHUNK_T; t++) {
        const __half* ptr = gz + (size_t)t * (B_DIM * N_DIM);
        float2 z = __half22float2(*(const __half2*)(ptr));
        float2 f = __half22float2(*(const __half2*)(ptr + H_DIM));
        c.x = fmaf(f.x, z.x - c.x, c.x);
        c.y = fmaf(f.y, z.y - c.y, c.y);
        p.x *= (1.0f - f.x);
        p.y *= (1.0f - f.y);
    }
    *(float2*)&P[(size_t)s * NCH + 2 * j2] = p;
    *(float2*)&Q[(size_t)s * NCH + 2 * j2] = c;
}

// pass2: combine predecessor maps, rescan, emit o*c
__global__ void scan_pass2(const __half* __restrict__ G,
                           const float* __restrict__ P, const float* __restrict__ Q,
                           float* __restrict__ outf, __half* __restrict__ outh,
                           int Tout, int write_half)
{
    const int id = blockIdx.x * blockDim.x + threadIdx.x;
    const int j2 = id & (NPAIR - 1);
    const int s  = id >> 13;
    const int b  = j2 >> 9;
    const int hh = (j2 & 511) * 2;

    float2 c = {0.0f, 0.0f};
    for (int ss = 0; ss < s; ss++) {
        float2 p2 = *(const float2*)&P[(size_t)ss * NCH + 2 * j2];
        float2 q2 = *(const float2*)&Q[(size_t)ss * NCH + 2 * j2];
        c.x = fmaf(p2.x, c.x, q2.x);
        c.y = fmaf(p2.y, c.y, q2.y);
    }

    const __half* gz = G + ((size_t)(s * CHUNK_T) * B_DIM + b) * N_DIM + hh;
    const size_t obase = ((size_t)(s * CHUNK_T) * B_DIM + b) * H_DIM + hh;
    const int tmax = Tout - s * CHUNK_T;
    #pragma unroll 8
    for (int t = 0; t < CHUNK_T; t++) {
        const __half* ptr = gz + (size_t)t * (B_DIM * N_DIM);
        float2 z = __half22float2(*(const __half2*)(ptr));
        float2 f = __half22float2(*(const __half2*)(ptr + H_DIM));
        float2 o = __half22float2(*(const __half2*)(ptr + 2 * H_DIM));
        c.x = fmaf(f.x, z.x - c.x, c.x);
        c.y = fmaf(f.y, z.y - c.y, c.y);
        if (t < tmax) {
            const size_t oi = obase + (size_t)t * (B_DIM * H_DIM);
            if (write_half)
                *(__half2*)&outh[oi] = __floats2half2_rn(o.x * c.x, o.y * c.y);
            else
                *(float2*)&outf[oi] = make_float2(o.x * c.x, o.y * c.y);
        }
    }
}

// ---------------------------------------------------------------------------
extern "C" void kernel_launch(void* const* d_in, const int* in_sizes, int n_in,
                              void* d_out, int out_size)
{
    const int*   x    = (const int*)  d_in[0];
    const float* emb  = (const float*)d_in[1];
    const float* W    = (const float*)d_in[2];
    const float* bias = (const float*)d_in[3];
    float* out = (float*)d_out;

    __half *h0, *h1, *Wt, *G;
    float *P, *Q;
    cudaGetSymbolAddress((void**)&h0, g_h0);
    cudaGetSymbolAddress((void**)&h1, g_h1);
    cudaGetSymbolAddress((void**)&G,  g_G);
    cudaGetSymbolAddress((void**)&Wt, g_Wt);
    cudaGetSymbolAddress((void**)&P,  g_P);
    cudaGetSymbolAddress((void**)&Q,  g_Q);

    static bool attr_set = false;
    if (!attr_set) {
        cudaFuncSetAttribute(gemm_tc_kernel,
                             cudaFuncAttributeMaxDynamicSharedMemorySize, SM_TOTAL);
        attr_set = true;
    }

    embed_kernel<<<(M_DIM * H_DIM / 4) / 256, 256>>>(x, emb, h0);
    transpose_kernel<<<dim3(N_DIM / 32, K_DIM / 32, L_DIM), dim3(32, 8)>>>(W, Wt);

    dim3 ggrid(N_DIM / BN, M_DIM / BM);                      // (24, 128)
    const int sgrid1 = ((S_CHUNKS - 1) * NPAIR) / 256;       // pass1: 480 blocks
    const int sgrid2 = (S_CHUNKS * NPAIR) / 256;             // pass2: 512 blocks

    gemm_tc_kernel<<<ggrid, 256, SM_TOTAL>>>(h0, Wt + 0 * (size_t)N_DIM * K_DIM,
                                             bias + 0 * N_DIM, G);
    scan_pass1<<<sgrid1, 256>>>(G, P, Q);
    scan_pass2<<<sgrid2, 256>>>(G, P, Q, nullptr, h1, T_DIM, 1);

    gemm_tc_kernel<<<ggrid, 256, SM_TOTAL>>>(h1, Wt + 1 * (size_t)N_DIM * K_DIM,
                                             bias + 1 * N_DIM, G);
    scan_pass1<<<sgrid1, 256>>>(G, P, Q);
    scan_pass2<<<sgrid2, 256>>>(G, P, Q, nullptr, h0, T_DIM, 1);

    gemm_tc_kernel<<<ggrid, 256, SM_TOTAL>>>(h0, Wt + 2 * (size_t)N_DIM * K_DIM,
                                             bias + 2 * N_DIM, G);
    scan_pass1<<<sgrid1, 256>>>(G, P, Q);
    scan_pass2<<<sgrid2, 256>>>(G, P, Q, out, nullptr, T_DIM - 1, 0);
}

// round 15
// speedup vs baseline: 1.0591x; 1.0348x over previous
#include <cuda_runtime.h>
#include <cuda_fp16.h>
#include <cstdint>
#include <math.h>

// Problem dims
#define T_DIM 1024
#define B_DIM 16
#define H_DIM 1024
#define L_DIM 3
#define M_DIM (T_DIM * B_DIM)   // 16384
#define N_DIM (3 * H_DIM)       // 3072
#define K_DIM H_DIM             // 1024
#define NCH   (B_DIM * H_DIM)   // 16384 scan channels
#define NPAIR (NCH / 2)         // 8192 channel pairs

// GEMM tiling (fp16 operands, fp32 accum) — best-known shape
#define BM 128
#define BN 128
#define BK 64
#define K_ITERS (K_DIM / BK)     // 16
#define WM 64
#define WN 32
#define MT (WM / 16)             // 4
#define NT (WN / 8)              // 4
#define ROWB 144                 // bytes per SMEM row (72 halves, padded)
#define TILE_BYTES (128 * ROWB)
#define STAGE_BYTES (2 * TILE_BYTES)
#define STAGES 3
#define SM_TOTAL (STAGES * STAGE_BYTES)    // 110592

// Scan chunking (best-measured: 16)
#define S_CHUNKS 16
#define CHUNK_T (T_DIM / S_CHUNKS)  // 64

// Scratch (device globals, no runtime alloc)
__device__ __half g_h0[(size_t)M_DIM * H_DIM];
__device__ __half g_h1[(size_t)M_DIM * H_DIM];
__device__ __half g_G [(size_t)M_DIM * N_DIM];
__device__ __half g_Wt[(size_t)L_DIM * N_DIM * K_DIM];
__device__ float  g_P [(size_t)S_CHUNKS * NCH];
__device__ float  g_Q [(size_t)S_CHUNKS * NCH];

// ---------------------------------------------------------------------------
// PTX helpers (sm_80-era only; compute_103 target rejects tcgen05)
// ---------------------------------------------------------------------------
__device__ __forceinline__ uint32_t smem_to_u32(const void* p) {
    uint32_t a;
    asm("{ .reg .u64 t; cvta.to.shared.u64 t, %1; cvt.u32.u64 %0, t; }" : "=r"(a) : "l"(p));
    return a;
}
#define CP_ASYNC16(sa, gp) \
    asm volatile("cp.async.cg.shared.global [%0], [%1], 16;" :: "r"(sa), "l"(gp))
#define CP_COMMIT() asm volatile("cp.async.commit_group;" ::: "memory")
#define CP_WAIT1()  asm volatile("cp.async.wait_group 1;" ::: "memory")
#define CP_WAIT0()  asm volatile("cp.async.wait_group 0;" ::: "memory")

#define LDSM_X4(r0, r1, r2, r3, addr) \
    asm volatile("ldmatrix.sync.aligned.m8n8.x4.shared.b16 {%0,%1,%2,%3}, [%4];" \
                 : "=r"(r0), "=r"(r1), "=r"(r2), "=r"(r3) : "r"(addr))

__device__ __forceinline__ void mma_f16(float& c0, float& c1, float& c2, float& c3,
                                        uint32_t a0, uint32_t a1, uint32_t a2, uint32_t a3,
                                        uint32_t b0, uint32_t b1) {
    asm volatile("mma.sync.aligned.m16n8k16.row.col.f32.f16.f16.f32 "
                 "{%0,%1,%2,%3}, {%4,%5,%6,%7}, {%8,%9}, {%0,%1,%2,%3};"
                 : "+f"(c0), "+f"(c1), "+f"(c2), "+f"(c3)
                 : "r"(a0), "r"(a1), "r"(a2), "r"(a3), "r"(b0), "r"(b1));
}

// ---------------------------------------------------------------------------
// MUFU-based activations: ~2 MUFU + 4 FMA each (vs ~25 FMA for the old
// polynomial). ex2/rcp approx error ~2 ulp — negligible vs fp16 rounding.
// Saturation safe: ex2->inf => rcp->0 (no NaN).
// ---------------------------------------------------------------------------
__device__ __forceinline__ float mufu_ex2(float x) {
    float r;
    asm("ex2.approx.f32 %0, %1;" : "=f"(r) : "f"(x));
    return r;
}
__device__ __forceinline__ float mufu_rcp(float x) {
    float r;
    asm("rcp.approx.f32 %0, %1;" : "=f"(r) : "f"(x));
    return r;
}
__device__ __forceinline__ float tanh_fast(float x) {
    // tanh(x) = 1 - 2/(exp(2x)+1);  exp(2x) = 2^(2*log2(e)*x)
    float e = mufu_ex2(2.88539008f * x);
    return fmaf(-2.0f, mufu_rcp(e + 1.0f), 1.0f);
}
__device__ __forceinline__ float sigmoid_fast(float x) {
    // sigmoid(x) = 1/(1+exp(-x))
    float e = mufu_ex2(-1.44269504f * x);
    return mufu_rcp(1.0f + e);
}

// ---------------------------------------------------------------------------
// Embedding gather -> fp16 h buffer
// ---------------------------------------------------------------------------
__global__ void embed_kernel(const int* __restrict__ x,
                             const float* __restrict__ emb,
                             __half* __restrict__ h)
{
    int idx = blockIdx.x * blockDim.x + threadIdx.x;
    int i   = idx * 4;
    int tb  = i >> 10;
    int hh  = i & (H_DIM - 1);
    int tok = x[tb];
    float4 v = *(const float4*)(emb + (size_t)tok * H_DIM + hh);
    __half2 lo = __floats2half2_rn(v.x, v.y);
    __half2 hi = __floats2half2_rn(v.z, v.w);
    uint2 pk = { *(uint32_t*)&lo, *(uint32_t*)&hi };
    *(uint2*)(h + i) = pk;
}

// ---------------------------------------------------------------------------
// W transpose + fp16 round:  Wt[l][n][k] = half(W[l][k][n])
// ---------------------------------------------------------------------------
__global__ void transpose_kernel(const float* __restrict__ W, __half* __restrict__ Wt)
{
    __shared__ float tile[32][33];
    int l  = blockIdx.z;
    int n0 = blockIdx.x * 32;
    int k0 = blockIdx.y * 32;
    int tx = threadIdx.x, ty = threadIdx.y;
    #pragma unroll
    for (int j = 0; j < 32; j += 8) {
        int k = k0 + ty + j, n = n0 + tx;
        tile[ty + j][tx] = W[((size_t)l * K_DIM + k) * N_DIM + n];
    }
    __syncthreads();
    #pragma unroll
    for (int j = 0; j < 32; j += 8) {
        int n = n0 + ty + j, k = k0 + tx;
        Wt[((size_t)l * N_DIM + n) * K_DIM + k] = __float2half_rn(tile[tx][ty + j]);
    }
}

// ---------------------------------------------------------------------------
// FP16 tensor-core GEMM (best-known): 128x128 CTA, 8 warps (2x4), ldmatrix,
// 3-stage cp.async pipeline, fragment ping-pong. MUFU epilogue.
// ---------------------------------------------------------------------------
__global__ __launch_bounds__(256, 2)
void gemm_tc_kernel(const __half* __restrict__ A,
                    const __half* __restrict__ Bt,
                    const float* __restrict__ bias,
                    __half* __restrict__ C)
{
    extern __shared__ char smem[];

    const int tid = threadIdx.x;
    const int wid = tid >> 5;
    const int lid = tid & 31;
    const int g   = lid >> 2;
    const int t   = lid & 3;
    const int bm  = blockIdx.y * BM;
    const int bn  = blockIdx.x * BN;
    const int wm  = (wid >> 2) * WM;
    const int wn  = (wid & 3) * WN;

    const int l_row = tid >> 3;
    const int l_cir = tid & 7;
    const __half* Ag = A  + (size_t)(bm + l_row) * K_DIM + l_cir * 8;
    const __half* Bg = Bt + (size_t)(bn + l_row) * K_DIM + l_cir * 8;
    const uint32_t smem_base = smem_to_u32(smem);
    const uint32_t sAo = smem_base + l_row * ROWB + l_cir * 16;
    const uint32_t sBo = sAo + TILE_BYTES;

    const int r8 = lid & 7;
    const int q  = lid >> 3;
    uint32_t aoff[MT], boff[NT / 2];
    #pragma unroll
    for (int mt = 0; mt < MT; mt++)
        aoff[mt] = (uint32_t)((wm + mt * 16 + r8 + (q & 1) * 8) * ROWB + (q >> 1) * 16);
    #pragma unroll
    for (int p = 0; p < NT / 2; p++)
        boff[p] = (uint32_t)(TILE_BYTES + (wn + p * 16 + r8 + (q >> 1) * 8) * ROWB
                             + (q & 1) * 16);

    float acc[MT][NT][4];
    #pragma unroll
    for (int i = 0; i < MT; i++)
        #pragma unroll
        for (int j = 0; j < NT; j++)
            #pragma unroll
            for (int r = 0; r < 4; r++) acc[i][j][r] = 0.0f;

    #pragma unroll
    for (int p = 0; p < 2; p++) {
        const uint32_t soff = p * STAGE_BYTES;
        const __half* Ak = Ag + p * BK;
        const __half* Bk = Bg + p * BK;
        #pragma unroll
        for (int j = 0; j < 4; j++) {
            CP_ASYNC16(sAo + soff + j * 32 * ROWB, Ak + (size_t)(j * 32) * K_DIM);
            CP_ASYNC16(sBo + soff + j * 32 * ROWB, Bk + (size_t)(j * 32) * K_DIM);
        }
        CP_COMMIT();
    }

    int stg = 0, wst = 2;
    for (int i = 0; i < K_ITERS; i++) {
        if (i + 1 < K_ITERS) CP_WAIT1(); else CP_WAIT0();
        __syncthreads();

        if (i + 2 < K_ITERS) {
            const uint32_t soff = wst * STAGE_BYTES;
            const __half* Ak = Ag + (i + 2) * BK;
            const __half* Bk = Bg + (i + 2) * BK;
            #pragma unroll
            for (int j = 0; j < 4; j++) {
                CP_ASYNC16(sAo + soff + j * 32 * ROWB, Ak + (size_t)(j * 32) * K_DIM);
                CP_ASYNC16(sBo + soff + j * 32 * ROWB, Bk + (size_t)(j * 32) * K_DIM);
            }
            CP_COMMIT();
        }

        const uint32_t sbase = smem_base + stg * STAGE_BYTES;

        uint32_t af[2][MT][4], bf[2][NT][2];
        #pragma unroll
        for (int mt = 0; mt < MT; mt++)
            LDSM_X4(af[0][mt][0], af[0][mt][1], af[0][mt][2], af[0][mt][3],
                    sbase + aoff[mt]);
        #pragma unroll
        for (int p = 0; p < NT / 2; p++)
            LDSM_X4(bf[0][2*p][0], bf[0][2*p][1], bf[0][2*p+1][0], bf[0][2*p+1][1],
                    sbase + boff[p]);

        #pragma unroll
        for (int ks = 0; ks < 4; ks++) {
            const int cur = ks & 1;
            const int nxt = cur ^ 1;
            if (ks < 3) {
                const uint32_t kb = (ks + 1) * 32;
                #pragma unroll
                for (int mt = 0; mt < MT; mt++)
                    LDSM_X4(af[nxt][mt][0], af[nxt][mt][1], af[nxt][mt][2], af[nxt][mt][3],
                            sbase + aoff[mt] + kb);
                #pragma unroll
                for (int p = 0; p < NT / 2; p++)
                    LDSM_X4(bf[nxt][2*p][0], bf[nxt][2*p][1],
                            bf[nxt][2*p+1][0], bf[nxt][2*p+1][1],
                            sbase + boff[p] + kb);
            }
            #pragma unroll
            for (int mt = 0; mt < MT; mt++)
                #pragma unroll
                for (int nt = 0; nt < NT; nt++)
                    mma_f16(acc[mt][nt][0], acc[mt][nt][1],
                            acc[mt][nt][2], acc[mt][nt][3],
                            af[cur][mt][0], af[cur][mt][1],
                            af[cur][mt][2], af[cur][mt][3],
                            bf[cur][nt][0], bf[cur][nt][1]);
        }

        stg = (stg == 2) ? 0 : stg + 1;
        wst = (wst == 2) ? 0 : wst + 1;
    }

    // epilogue: hoisted bias, MUFU activations, half2 stores
    float bw0[NT], bw1[NT];
    #pragma unroll
    for (int nt = 0; nt < NT; nt++) {
        const int col = bn + wn + nt * 8 + 2 * t;
        bw0[nt] = __ldg(&bias[col]);
        bw1[nt] = __ldg(&bias[col + 1]);
    }
    #pragma unroll
    for (int mt = 0; mt < MT; mt++) {
        const int row0 = bm + wm + mt * 16 + g;
        #pragma unroll
        for (int nt = 0; nt < NT; nt++) {
            const int col = bn + wn + nt * 8 + 2 * t;
            float2 v0, v1;
            if (col < H_DIM) {
                v0.x = tanh_fast(acc[mt][nt][0] + bw0[nt]);
                v0.y = tanh_fast(acc[mt][nt][1] + bw1[nt]);
                v1.x = tanh_fast(acc[mt][nt][2] + bw0[nt]);
                v1.y = tanh_fast(acc[mt][nt][3] + bw1[nt]);
            } else {
                v0.x = sigmoid_fast(acc[mt][nt][0] + bw0[nt]);
                v0.y = sigmoid_fast(acc[mt][nt][1] + bw1[nt]);
                v1.x = sigmoid_fast(acc[mt][nt][2] + bw0[nt]);
                v1.y = sigmoid_fast(acc[mt][nt][3] + bw1[nt]);
            }
            *(__half2*)&C[(size_t)row0 * N_DIM + col]       = __floats2half2_rn(v0.x, v0.y);
            *(__half2*)&C[(size_t)(row0 + 8) * N_DIM + col] = __floats2half2_rn(v1.x, v1.y);
        }
    }
}

// ---------------------------------------------------------------------------
// Chunked-parallel forget-mult scan over fp16 gates, half2 channel pairs.
// Two-pass; S_CHUNKS=16. pass1 skips the last chunk (map has no consumer).
// ---------------------------------------------------------------------------
__global__ void scan_pass1(const __half* __restrict__ G,
                           float* __restrict__ P, float* __restrict__ Q)
{
    const int id = blockIdx.x * blockDim.x + threadIdx.x;   // 0 .. (S-1)*NPAIR-1
    const int j2 = id & (NPAIR - 1);
    const int s  = id >> 13;
    const int b  = j2 >> 9;
    const int hh = (j2 & 511) * 2;
    const __half* gz = G + ((size_t)(s * CHUNK_T) * B_DIM + b) * N_DIM + hh;

    float2 c = {0.0f, 0.0f}, p = {1.0f, 1.0f};
    #pragma unroll 8
    for (int t = 0; t < CHUNK_T; t++) {
        const __half* ptr = gz + (size_t)t * (B_DIM * N_DIM);
        float2 z = __half22float2(*(const __half2*)(ptr));
        float2 f = __half22float2(*(const __half2*)(ptr + H_DIM));
        c.x = fmaf(f.x, z.x - c.x, c.x);
        c.y = fmaf(f.y, z.y - c.y, c.y);
        p.x *= (1.0f - f.x);
        p.y *= (1.0f - f.y);
    }
    *(float2*)&P[(size_t)s * NCH + 2 * j2] = p;
    *(float2*)&Q[(size_t)s * NCH + 2 * j2] = c;
}

// pass2: combine predecessor maps, rescan, emit o*c
__global__ void scan_pass2(const __half* __restrict__ G,
                           const float* __restrict__ P, const float* __restrict__ Q,
                           float* __restrict__ outf, __half* __restrict__ outh,
                           int Tout, int write_half)
{
    const int id = blockIdx.x * blockDim.x + threadIdx.x;
    const int j2 = id & (NPAIR - 1);
    const int s  = id >> 13;
    const int b  = j2 >> 9;
    const int hh = (j2 & 511) * 2;

    float2 c = {0.0f, 0.0f};
    for (int ss = 0; ss < s; ss++) {
        float2 p2 = *(const float2*)&P[(size_t)ss * NCH + 2 * j2];
        float2 q2 = *(const float2*)&Q[(size_t)ss * NCH + 2 * j2];
        c.x = fmaf(p2.x, c.x, q2.x);
        c.y = fmaf(p2.y, c.y, q2.y);
    }

    const __half* gz = G + ((size_t)(s * CHUNK_T) * B_DIM + b) * N_DIM + hh;
    const size_t obase = ((size_t)(s * CHUNK_T) * B_DIM + b) * H_DIM + hh;
    const int tmax = Tout - s * CHUNK_T;
    #pragma unroll 8
    for (int t = 0; t < CHUNK_T; t++) {
        const __half* ptr = gz + (size_t)t * (B_DIM * N_DIM);
        float2 z = __half22float2(*(const __half2*)(ptr));
        float2 f = __half22float2(*(const __half2*)(ptr + H_DIM));
        float2 o = __half22float2(*(const __half2*)(ptr + 2 * H_DIM));
        c.x = fmaf(f.x, z.x - c.x, c.x);
        c.y = fmaf(f.y, z.y - c.y, c.y);
        if (t < tmax) {
            const size_t oi = obase + (size_t)t * (B_DIM * H_DIM);
            if (write_half)
                *(__half2*)&outh[oi] = __floats2half2_rn(o.x * c.x, o.y * c.y);
            else
                *(float2*)&outf[oi] = make_float2(o.x * c.x, o.y * c.y);
        }
    }
}

// ---------------------------------------------------------------------------
extern "C" void kernel_launch(void* const* d_in, const int* in_sizes, int n_in,
                              void* d_out, int out_size)
{
    const int*   x    = (const int*)  d_in[0];
    const float* emb  = (const float*)d_in[1];
    const float* W    = (const float*)d_in[2];
    const float* bias = (const float*)d_in[3];
    float* out = (float*)d_out;

    __half *h0, *h1, *Wt, *G;
    float *P, *Q;
    cudaGetSymbolAddress((void**)&h0, g_h0);
    cudaGetSymbolAddress((void**)&h1, g_h1);
    cudaGetSymbolAddress((void**)&G,  g_G);
    cudaGetSymbolAddress((void**)&Wt, g_Wt);
    cudaGetSymbolAddress((void**)&P,  g_P);
    cudaGetSymbolAddress((void**)&Q,  g_Q);

    static bool attr_set = false;
    if (!attr_set) {
        cudaFuncSetAttribute(gemm_tc_kernel,
                             cudaFuncAttributeMaxDynamicSharedMemorySize, SM_TOTAL);
        attr_set = true;
    }

    embed_kernel<<<(M_DIM * H_DIM / 4) / 256, 256>>>(x, emb, h0);
    transpose_kernel<<<dim3(N_DIM / 32, K_DIM / 32, L_DIM), dim3(32, 8)>>>(W, Wt);

    dim3 ggrid(N_DIM / BN, M_DIM / BM);                      // (24, 128)
    const int sgrid1 = ((S_CHUNKS - 1) * NPAIR) / 256;       // pass1: 480 blocks
    const int sgrid2 = (S_CHUNKS * NPAIR) / 256;             // pass2: 512 blocks

    gemm_tc_kernel<<<ggrid, 256, SM_TOTAL>>>(h0, Wt + 0 * (size_t)N_DIM * K_DIM,
                                             bias + 0 * N_DIM, G);
    scan_pass1<<<sgrid1, 256>>>(G, P, Q);
    scan_pass2<<<sgrid2, 256>>>(G, P, Q, nullptr, h1, T_DIM, 1);

    gemm_tc_kernel<<<ggrid, 256, SM_TOTAL>>>(h1, Wt + 1 * (size_t)N_DIM * K_DIM,
                                             bias + 1 * N_DIM, G);
    scan_pass1<<<sgrid1, 256>>>(G, P, Q);
    scan_pass2<<<sgrid2, 256>>>(G, P, Q, nullptr, h0, T_DIM, 1);

    gemm_tc_kernel<<<ggrid, 256, SM_TOTAL>>>(h0, Wt + 2 * (size_t)N_DIM * K_DIM,
                                             bias + 2 * N_DIM, G);
    scan_pass1<<<sgrid1, 256>>>(G, P, Q);
    scan_pass2<<<sgrid2, 256>>>(G, P, Q, out, nullptr, T_DIM - 1, 0);
}